// round 6
// baseline (speedup 1.0000x reference)
#include <cuda_runtime.h>
#include <cuda_bf16.h>
#include <math.h>
#include <stdint.h>

#define BB 32
#define TT 1500
#define HH 768
#define HM1 767
#define LQ 400
#define MM (BB*LQ)                 /* 12800 */
#define FC_OFF ((size_t)MM*HH)
#define NHAT_OFF ((size_t)2*MM*HH)
#define P_MIX_C 0.15f

#define NRB 100                    /* 128-row blocks */
#define NCB 6                      /* 128-col blocks */
#define TILES1 (NRB*NCB)           /* 600 */
#define TILES_ALL (2*TILES1)       /* 1200 */
#define NCTA 148

// ---------------- scratch (__device__ globals, no allocs) ------------------
__device__ float g_scale[BB];
__device__ float g_nhat_part[BB];
__device__ int   g_tilectr;
__device__ int   g_ready[NRB];
__device__ __nv_bfloat16 g_sa_hi[(size_t)MM * HH];
__device__ __nv_bfloat16 g_sa_lo[(size_t)MM * HH];
__device__ __nv_bfloat16 g_y1_hi[(size_t)MM * HH];
__device__ __nv_bfloat16 g_y1_lo[(size_t)MM * HH];
__device__ __nv_bfloat16 g_w1t_hi[(size_t)HH * HH];
__device__ __nv_bfloat16 g_w1t_lo[(size_t)HH * HH];
__device__ __nv_bfloat16 g_w2t_hi[(size_t)HH * HH];
__device__ __nv_bfloat16 g_w2t_lo[(size_t)HH * HH];

// ---------------- helpers --------------------------------------------------
__device__ __forceinline__ uint32_t smem_u32(const void* p) {
    uint32_t a;
    asm("{ .reg .u64 t; cvta.to.shared.u64 t, %1; cvt.u32.u64 %0, t; }"
        : "=r"(a) : "l"(p));
    return a;
}
__device__ __forceinline__ void split_bf16(float v, __nv_bfloat16& h, __nv_bfloat16& l) {
    h = __float2bfloat16(v);
    l = __float2bfloat16(v - __bfloat162float(h));
}
__device__ __forceinline__ uint32_t pack2(__nv_bfloat16 a, __nv_bfloat16 b) {
    return (uint32_t)__bfloat16_as_ushort(a) |
           ((uint32_t)__bfloat16_as_ushort(b) << 16);
}
__device__ __forceinline__ int ld_acquire(const int* p) {
    int v;
    asm volatile("ld.global.acquire.gpu.b32 %0, [%1];" : "=r"(v) : "l"(p) : "memory");
    return v;
}

#define CP16(d, s) \
    asm volatile("cp.async.cg.shared.global [%0], [%1], 16;" :: "r"(d), "l"(s))
#define CP_COMMIT() asm volatile("cp.async.commit_group;" ::: "memory")
#define CP_WAIT(n)  asm volatile("cp.async.wait_group %0;" :: "n"(n) : "memory")

#define LDM4(r, addr) \
    asm volatile("ldmatrix.sync.aligned.m8n8.x4.shared.b16 {%0,%1,%2,%3},[%4];" \
        : "=r"((r)[0]), "=r"((r)[1]), "=r"((r)[2]), "=r"((r)[3]) : "r"(addr))

#define MMA(d, a, b) \
    asm volatile("mma.sync.aligned.m16n8k16.row.col.f32.bf16.bf16.f32 " \
        "{%0,%1,%2,%3},{%4,%5,%6,%7},{%8,%9},{%0,%1,%2,%3};" \
        : "+f"((d)[0]), "+f"((d)[1]), "+f"((d)[2]), "+f"((d)[3]) \
        : "r"((a)[0]), "r"((a)[1]), "r"((a)[2]), "r"((a)[3]), \
          "r"((b)[0]), "r"((b)[1]))

// ---------------------------------------------------------------------------
__global__ void reset_kernel() {
    if (threadIdx.x == 0) g_tilectr = 0;
    if (threadIdx.x < NRB) g_ready[threadIdx.x] = 0;
}

// ---------------------------------------------------------------------------
__global__ void alpha_kernel(const float* __restrict__ hs,
                             const int* __restrict__ lengths) {
    int b = blockIdx.x;
    const float* base = hs + (size_t)b * TT * HH + (HH - 1);
    float s = 0.f;
    for (int t = threadIdx.x; t < TT; t += blockDim.x)
        s += 1.f / (1.f + expf(-base[(size_t)t * HH]));
    __shared__ float red[256];
    red[threadIdx.x] = s;
    __syncthreads();
    for (int o = 128; o > 0; o >>= 1) {
        if (threadIdx.x < o) red[threadIdx.x] += red[threadIdx.x + o];
        __syncthreads();
    }
    if (threadIdx.x == 0) {
        float sum = red[0];
        int li = lengths[b];
        float tll = (float)(li < LQ ? li : LQ);
        g_scale[b] = tll / sum;
        float d = tll - sum;
        g_nhat_part[b] = d * d;
    }
}
__global__ void nhat_kernel(float* __restrict__ out) {
    float v = g_nhat_part[threadIdx.x];
    #pragma unroll
    for (int o = 16; o > 0; o >>= 1) v += __shfl_down_sync(0xffffffffu, v, o);
    if (threadIdx.x == 0) out[0] = v;
}

// ---------------------------------------------------------------------------
__global__ void cif_scan_kernel(const float* __restrict__ hs) {
    int b = blockIdx.y;
    int f = blockIdx.x * blockDim.x + threadIdx.x;
    __shared__ float s_alpha[LQ];
    float scale = g_scale[b];
    const float* hb = hs + (size_t)b * TT * HH;
    for (int t = threadIdx.x; t < LQ; t += blockDim.x)
        s_alpha[t] = scale / (1.f + expf(-hb[(size_t)t * HH + (HH - 1)]));
    __syncthreads();

    bool valid = (f < HM1);
    const float* hcol = hb + f;
    size_t obase = (size_t)b * LQ * HH + f;

    float a_r = 0.f, s_r = 0.f;
    float h = valid ? hcol[0] : 0.f;
    for (int t = 0; t < LQ; ++t) {
        float hn = valid ? hcol[(size_t)(t + 1) * HH] : 0.f;
        float a = s_alpha[t];
        float a_a = a + a_r;
        float rem = 1.0f - a_r;
        float s_a_nf = s_r + a * h;
        float s_a;
        if (a_a >= 1.0f) {
            float a_r_f = a - rem;
            s_a = s_r + rem * h;
            a_r = a_r_f;
            s_r = a_r_f * h;
        } else {
            a_r = a_a; s_a = s_a_nf; s_r = s_a_nf;
        }
        __nv_bfloat16 hi, lo;
        split_bf16(s_a, hi, lo);
        g_sa_hi[obase + (size_t)t * HH] = hi;
        g_sa_lo[obase + (size_t)t * HH] = lo;
        h = hn;
    }
}

// ---------------------------------------------------------------------------
__global__ void wtrans_kernel(const float* __restrict__ W,
                              __nv_bfloat16* __restrict__ Wt_hi,
                              __nv_bfloat16* __restrict__ Wt_lo, int Kvalid) {
    __shared__ float t[32][33];
    int n = blockIdx.x * 32 + threadIdx.x;
    #pragma unroll
    for (int j = 0; j < 32; j += 8) {
        int k = blockIdx.y * 32 + threadIdx.y + j;
        t[threadIdx.y + j][threadIdx.x] = (k < Kvalid) ? W[(size_t)k * HH + n] : 0.f;
    }
    __syncthreads();
    #pragma unroll
    for (int j = 0; j < 32; j += 8) {
        int nn = blockIdx.x * 32 + threadIdx.y + j;
        int kk = blockIdx.y * 32 + threadIdx.x;
        __nv_bfloat16 hi, lo;
        split_bf16(t[threadIdx.x][threadIdx.y + j], hi, lo);
        Wt_hi[(size_t)nn * HH + kk] = hi;
        Wt_lo[(size_t)nn * HH + kk] = lo;
    }
}

// ---------------------------------------------------------------------------
// Fused persistent GEMM: 148 CTAs x 512 thr, dynamic tile counter over 1200
// tile-units. t<600: GEMM1 (sa@W1 -> relu -> y1 hi/lo) + readiness flag.
// t>=600: GEMM2 (y1@W2 -> fc + bert_mixing), gated on ready[rb]==6 with
// read-only acquire polling + nanosleep backoff (no atomic-RMW hammering).
// ---------------------------------------------------------------------------
#define KCH 64
#define NCHUNK (HH / KCH)            /* 12 */
#define MAT_BYTES 16384
#define STAGE_BYTES (4 * MAT_BYTES)
#define SMEM_SZ (2 * STAGE_BYTES)    /* 131072 */

__global__ void __launch_bounds__(512, 1)
gemm_fused(const __nv_bfloat16* __restrict__ sahi, const __nv_bfloat16* __restrict__ salo,
           const __nv_bfloat16* __restrict__ w1h, const __nv_bfloat16* __restrict__ w1l,
           const __nv_bfloat16* __restrict__ w2h, const __nv_bfloat16* __restrict__ w2l,
           const float* __restrict__ b1, const float* __restrict__ b2,
           __nv_bfloat16* __restrict__ yhi, __nv_bfloat16* __restrict__ ylo,
           float* __restrict__ outbm, float* __restrict__ fcout,
           const float* __restrict__ bert, const float* __restrict__ mixu) {
    extern __shared__ char smem[];
    __shared__ int sh_t;
    uint32_t sb = smem_u32(smem);
    int tid = threadIdx.x, lane = tid & 31, wid = tid >> 5;
    int wr = wid >> 2, wc = wid & 3;

    int cr = tid >> 3, cu = tid & 7;
    int a_row = lane & 15;
    int a_un  = lane >> 4;
    int b_row = (lane & 7) + ((lane & 16) >> 1);
    int b_un  = (lane & 8) >> 3;
    int tr = lane >> 2;
    int tc = (lane & 3) * 2;

    for (;;) {
        if (tid == 0) sh_t = atomicAdd(&g_tilectr, 1);
        __syncthreads();
        int t = sh_t;
        if (t >= TILES_ALL) break;

        int is1 = (t < TILES1);
        int u = is1 ? t : t - TILES1;
        int rb = u / NCB, cb = u % NCB;
        int row0 = rb * 128, col0 = cb * 128;

        const __nv_bfloat16* Ahi = is1 ? sahi : yhi;
        const __nv_bfloat16* Alo = is1 ? salo : ylo;
        const __nv_bfloat16* Bhi = is1 ? w1h : w2h;
        const __nv_bfloat16* Blo = is1 ? w1l : w2l;
        const float* bias = is1 ? b1 : b2;

        if (!is1) {
            if (tid == 0) {
                while (ld_acquire(&g_ready[rb]) < NCB) __nanosleep(200);
            }
            __syncthreads();
        }

        float acc[2][4][4];
        #pragma unroll
        for (int i = 0; i < 2; ++i)
            #pragma unroll
            for (int j = 0; j < 4; ++j)
                #pragma unroll
                for (int d = 0; d < 4; ++d) acc[i][j][d] = 0.f;

        #define LOAD_CHUNK(s, ci) do {                                        \
            int k0e = (ci) * KCH;                                             \
            uint32_t db = sb + (s) * STAGE_BYTES;                             \
            _Pragma("unroll")                                                 \
            for (int q = 0; q < 2; ++q) {                                     \
                int r = cr + q * 64;                                          \
                uint32_t d = db + r * 128 + ((cu ^ (r & 7)) << 4);            \
                size_t eA = (size_t)(row0 + r) * HH + k0e + cu * 8;           \
                size_t eB = (size_t)(col0 + r) * HH + k0e + cu * 8;           \
                CP16(d,                 (const char*)(Ahi + eA));             \
                CP16(d + MAT_BYTES,     (const char*)(Alo + eA));             \
                CP16(d + 2 * MAT_BYTES, (const char*)(Bhi + eB));             \
                CP16(d + 3 * MAT_BYTES, (const char*)(Blo + eB));             \
            }                                                                 \
            CP_COMMIT();                                                      \
        } while (0)

        LOAD_CHUNK(0, 0);

        for (int i = 0; i < NCHUNK; ++i) {
            if (i < NCHUNK - 1) { LOAD_CHUNK((i + 1) & 1, i + 1); CP_WAIT(1); }
            else                { CP_WAIT(0); }
            __syncthreads();

            uint32_t base = sb + (i & 1) * STAGE_BYTES;
            #pragma unroll
            for (int kk = 0; kk < KCH; kk += 16) {
                uint32_t ah[2][4], al[2][4], bh[4][2], bl[4][2];
                #pragma unroll
                for (int m = 0; m < 2; ++m) {
                    int r = wr * 32 + m * 16 + a_row;
                    int un = (kk >> 3) + a_un;
                    uint32_t off = base + r * 128 + ((un ^ (r & 7)) << 4);
                    LDM4(ah[m], off);
                    LDM4(al[m], off + MAT_BYTES);
                }
                #pragma unroll
                for (int jp = 0; jp < 2; ++jp) {
                    int r = wc * 32 + jp * 16 + b_row;
                    int un = (kk >> 3) + b_un;
                    uint32_t off = base + 2 * MAT_BYTES + r * 128 + ((un ^ (r & 7)) << 4);
                    uint32_t t0[4], t1[4];
                    LDM4(t0, off);
                    LDM4(t1, off + MAT_BYTES);
                    bh[2*jp][0] = t0[0]; bh[2*jp][1] = t0[1];
                    bh[2*jp+1][0] = t0[2]; bh[2*jp+1][1] = t0[3];
                    bl[2*jp][0] = t1[0]; bl[2*jp][1] = t1[1];
                    bl[2*jp+1][0] = t1[2]; bl[2*jp+1][1] = t1[3];
                }
                #pragma unroll
                for (int m = 0; m < 2; ++m)
                    #pragma unroll
                    for (int j = 0; j < 4; ++j) {
                        MMA(acc[m][j], ah[m], bh[j]);
                        MMA(acc[m][j], ah[m], bl[j]);
                        MMA(acc[m][j], al[m], bh[j]);
                    }
            }
            __syncthreads();
        }

        // ---- epilogue ----
        #pragma unroll
        for (int m = 0; m < 2; ++m) {
            #pragma unroll
            for (int half = 0; half < 2; ++half) {
                int row = row0 + wr * 32 + m * 16 + half * 8 + tr;
                float msk = 0.f;
                if (!is1) msk = (mixu[row] < P_MIX_C) ? 1.f : 0.f;
                #pragma unroll
                for (int j = 0; j < 4; ++j) {
                    int col = col0 + wc * 32 + j * 8 + tc;
                    float v0 = acc[m][j][half * 2 + 0] + bias[col];
                    float v1 = acc[m][j][half * 2 + 1] + bias[col + 1];
                    size_t idx = (size_t)row * HH + col;
                    if (is1) {
                        v0 = fmaxf(v0, 0.f); v1 = fmaxf(v1, 0.f);
                        __nv_bfloat16 h0, l0, h1, l1;
                        split_bf16(v0, h0, l0);
                        split_bf16(v1, h1, l1);
                        *(uint32_t*)(yhi + idx) = pack2(h0, h1);
                        *(uint32_t*)(ylo + idx) = pack2(l0, l1);
                    } else {
                        float2 fcv = make_float2(v0, v1);
                        *(float2*)(fcout + idx) = fcv;
                        float2 bm = fcv;
                        if (msk != 0.f) bm = *(const float2*)(bert + idx);
                        *(float2*)(outbm + idx) = bm;
                    }
                }
            }
        }

        if (is1) {
            __threadfence();            // order y1 stores before flag publish
            __syncthreads();
            if (tid == 0) atomicAdd(&g_ready[rb], 1);
        }
    }
}

// ---------------------------------------------------------------------------
extern "C" void kernel_launch(void* const* d_in, const int* in_sizes, int n_in,
                              void* d_out, int out_size) {
    const float* hs      = (const float*)d_in[0];
    const int*   lengths = (const int*)  d_in[1];
    const float* W1      = (const float*)d_in[2];
    const float* b1      = (const float*)d_in[3];
    const float* W2      = (const float*)d_in[4];
    const float* b2      = (const float*)d_in[5];
    const float* bert    = (const float*)d_in[6];
    const float* mixu    = (const float*)d_in[7];
    float* out = (float*)d_out;

    __nv_bfloat16 *sahi, *salo, *y1hi, *y1lo, *w1h, *w1l, *w2h, *w2l;
    cudaGetSymbolAddress((void**)&sahi, g_sa_hi);
    cudaGetSymbolAddress((void**)&salo, g_sa_lo);
    cudaGetSymbolAddress((void**)&y1hi, g_y1_hi);
    cudaGetSymbolAddress((void**)&y1lo, g_y1_lo);
    cudaGetSymbolAddress((void**)&w1h, g_w1t_hi);
    cudaGetSymbolAddress((void**)&w1l, g_w1t_lo);
    cudaGetSymbolAddress((void**)&w2h, g_w2t_hi);
    cudaGetSymbolAddress((void**)&w2l, g_w2t_lo);

    cudaFuncSetAttribute(gemm_fused, cudaFuncAttributeMaxDynamicSharedMemorySize, SMEM_SZ);

    reset_kernel<<<1, 128>>>();
    alpha_kernel<<<BB, 256>>>(hs, lengths);
    nhat_kernel<<<1, 32>>>(out + NHAT_OFF);
    wtrans_kernel<<<dim3(24, 24), dim3(32, 8)>>>(W1, w1h, w1l, HM1);
    wtrans_kernel<<<dim3(24, 24), dim3(32, 8)>>>(W2, w2h, w2l, HH);
    cif_scan_kernel<<<dim3(3, BB), 256>>>(hs);

    gemm_fused<<<NCTA, 512, SMEM_SZ>>>(
        sahi, salo, w1h, w1l, w2h, w2l, b1, b2,
        y1hi, y1lo, out /*bert_mixing*/, out + FC_OFF /*fc*/, bert, mixu);
}

// round 7
// speedup vs baseline: 1.3215x; 1.3215x over previous
#include <cuda_runtime.h>
#include <cuda_fp16.h>
#include <math.h>
#include <stdint.h>

#define BB 32
#define TT 1500
#define HH 768
#define HM1 767
#define LQ 400
#define MM (BB*LQ)                 /* 12800 */
#define FC_OFF ((size_t)MM*HH)
#define NHAT_OFF ((size_t)2*MM*HH)
#define P_MIX_C 0.15f

// ---------------- scratch (__device__ globals, no allocs) ------------------
__device__ float g_scale[BB];
__device__ float g_nhat_part[BB];
__device__ __half g_sa_hi[(size_t)MM * HH];
__device__ __half g_sa_lo[(size_t)MM * HH];
__device__ __half g_y1_hi[(size_t)MM * HH];
__device__ __half g_y1_lo[(size_t)MM * HH];
__device__ __half g_w1t_hi[(size_t)HH * HH];
__device__ __half g_w2t_hi[(size_t)HH * HH];

// ---------------- helpers --------------------------------------------------
__device__ __forceinline__ uint32_t smem_u32(const void* p) {
    uint32_t a;
    asm("{ .reg .u64 t; cvta.to.shared.u64 t, %1; cvt.u32.u64 %0, t; }"
        : "=r"(a) : "l"(p));
    return a;
}
__device__ __forceinline__ void split_f16(float v, __half& h, __half& l) {
    h = __float2half_rn(v);
    l = __float2half_rn(v - __half2float(h));
}
__device__ __forceinline__ uint32_t pack2h(__half a, __half b) {
    return (uint32_t)__half_as_ushort(a) |
           ((uint32_t)__half_as_ushort(b) << 16);
}

#define CP16(d, s) \
    asm volatile("cp.async.cg.shared.global [%0], [%1], 16;" :: "r"(d), "l"(s))
#define CP_COMMIT() asm volatile("cp.async.commit_group;" ::: "memory")
#define CP_WAIT(n)  asm volatile("cp.async.wait_group %0;" :: "n"(n) : "memory")

#define LDM4(r, addr) \
    asm volatile("ldmatrix.sync.aligned.m8n8.x4.shared.b16 {%0,%1,%2,%3},[%4];" \
        : "=r"((r)[0]), "=r"((r)[1]), "=r"((r)[2]), "=r"((r)[3]) : "r"(addr))

#define MMAH(d, a, b) \
    asm volatile("mma.sync.aligned.m16n8k16.row.col.f32.f16.f16.f32 " \
        "{%0,%1,%2,%3},{%4,%5,%6,%7},{%8,%9},{%0,%1,%2,%3};" \
        : "+f"((d)[0]), "+f"((d)[1]), "+f"((d)[2]), "+f"((d)[3]) \
        : "r"((a)[0]), "r"((a)[1]), "r"((a)[2]), "r"((a)[3]), \
          "r"((b)[0]), "r"((b)[1]))

// ---------------------------------------------------------------------------
// Kernel 1: per-batch alpha sum, scale, n_hat partial
// ---------------------------------------------------------------------------
__global__ void alpha_kernel(const float* __restrict__ hs,
                             const int* __restrict__ lengths) {
    int b = blockIdx.x;
    const float* base = hs + (size_t)b * TT * HH + (HH - 1);
    float s = 0.f;
    for (int t = threadIdx.x; t < TT; t += blockDim.x)
        s += 1.f / (1.f + expf(-base[(size_t)t * HH]));
    __shared__ float red[256];
    red[threadIdx.x] = s;
    __syncthreads();
    for (int o = 128; o > 0; o >>= 1) {
        if (threadIdx.x < o) red[threadIdx.x] += red[threadIdx.x + o];
        __syncthreads();
    }
    if (threadIdx.x == 0) {
        float sum = red[0];
        int li = lengths[b];
        float tll = (float)(li < LQ ? li : LQ);
        g_scale[b] = tll / sum;
        float d = tll - sum;
        g_nhat_part[b] = d * d;
    }
}
__global__ void nhat_kernel(float* __restrict__ out) {
    float v = g_nhat_part[threadIdx.x];
    #pragma unroll
    for (int o = 16; o > 0; o >>= 1) v += __shfl_down_sync(0xffffffffu, v, o);
    if (threadIdx.x == 0) out[0] = v;
}

// ---------------------------------------------------------------------------
// Kernel 2: CIF scan -> fp16 hi/lo planes. Pad lane 767 -> zeros.
// ---------------------------------------------------------------------------
__global__ void cif_scan_kernel(const float* __restrict__ hs) {
    int b = blockIdx.y;
    int f = blockIdx.x * blockDim.x + threadIdx.x;
    __shared__ float s_alpha[LQ];
    float scale = g_scale[b];
    const float* hb = hs + (size_t)b * TT * HH;
    for (int t = threadIdx.x; t < LQ; t += blockDim.x)
        s_alpha[t] = scale / (1.f + expf(-hb[(size_t)t * HH + (HH - 1)]));
    __syncthreads();

    bool valid = (f < HM1);
    const float* hcol = hb + f;
    size_t obase = (size_t)b * LQ * HH + f;

    float a_r = 0.f, s_r = 0.f;
    float h = valid ? hcol[0] : 0.f;
    for (int t = 0; t < LQ; ++t) {
        float hn = valid ? hcol[(size_t)(t + 1) * HH] : 0.f;
        float a = s_alpha[t];
        float a_a = a + a_r;
        float rem = 1.0f - a_r;
        float s_a_nf = s_r + a * h;
        float s_a;
        if (a_a >= 1.0f) {
            float a_r_f = a - rem;
            s_a = s_r + rem * h;
            a_r = a_r_f;
            s_r = a_r_f * h;
        } else {
            a_r = a_a; s_a = s_a_nf; s_r = s_a_nf;
        }
        __half hi, lo;
        split_f16(s_a, hi, lo);
        g_sa_hi[obase + (size_t)t * HH] = hi;
        g_sa_lo[obase + (size_t)t * HH] = lo;
        h = hn;
    }
}

// ---------------------------------------------------------------------------
// Kernel 3: W transpose: Wt[n][k] = fp16(W[k][n]), k>=Kvalid -> 0
// ---------------------------------------------------------------------------
__global__ void wtrans_kernel(const float* __restrict__ W,
                              __half* __restrict__ Wt_hi, int Kvalid) {
    __shared__ float t[32][33];
    int n = blockIdx.x * 32 + threadIdx.x;
    #pragma unroll
    for (int j = 0; j < 32; j += 8) {
        int k = blockIdx.y * 32 + threadIdx.y + j;
        t[threadIdx.y + j][threadIdx.x] = (k < Kvalid) ? W[(size_t)k * HH + n] : 0.f;
    }
    __syncthreads();
    #pragma unroll
    for (int j = 0; j < 32; j += 8) {
        int nn = blockIdx.x * 32 + threadIdx.y + j;
        int kk = blockIdx.y * 32 + threadIdx.x;
        Wt_hi[(size_t)nn * HH + kk] = __float2half_rn(t[threadIdx.x][threadIdx.y + j]);
    }
}

// ---------------------------------------------------------------------------
// Kernel 4: fp16 2-term split GEMM (C = Ahi*Bhi + Alo*Bhi). CTA tile 128x128,
// 512 threads / 16 warps (4x4, warp tile 32x32). K chunks of 64, 2-stage
// cp.async pipeline, XOR-swizzled SMEM.
// MODE 0: y1 = relu(A@B^T+b) -> fp16 hi/lo planes. MODE 1: fc + bert_mixing.
// ---------------------------------------------------------------------------
#define KCH 64
#define NCHUNK (HH / KCH)            /* 12 */
#define MAT_BYTES 16384              /* 128 rows x 128B */
#define STAGE_BYTES (3 * MAT_BYTES)  /* 49152: Ahi, Alo, Bhi */
#define SMEM_SZ (2 * STAGE_BYTES)    /* 98304 */

template <int MODE>
__global__ void __launch_bounds__(512, 1)
gemm_hmma(const __half* __restrict__ Ahi, const __half* __restrict__ Alo,
          const __half* __restrict__ Bhi,
          const float* __restrict__ bias,
          __half* __restrict__ yhi, __half* __restrict__ ylo,
          float* __restrict__ outbm, float* __restrict__ fcout,
          const float* __restrict__ bert, const float* __restrict__ mixu) {
    extern __shared__ char smem[];
    uint32_t sb = smem_u32(smem);
    int tid = threadIdx.x, lane = tid & 31, wid = tid >> 5;
    int row0 = blockIdx.y * 128, col0 = blockIdx.x * 128;
    int wr = wid >> 2, wc = wid & 3;     // warp tile: rows wr*32, cols wc*32

    float acc[2][4][4];
    #pragma unroll
    for (int i = 0; i < 2; ++i)
        #pragma unroll
        for (int j = 0; j < 4; ++j)
            #pragma unroll
            for (int d = 0; d < 4; ++d) acc[i][j][d] = 0.f;

    int cr = tid >> 3, cu = tid & 7;

    int a_row = lane & 15;
    int a_un  = lane >> 4;
    int b_row = (lane & 7) + ((lane & 16) >> 1);
    int b_un  = (lane & 8) >> 3;

    #define LOAD_CHUNK(s, ci) do {                                            \
        int k0e = (ci) * KCH;                                                 \
        uint32_t db = sb + (s) * STAGE_BYTES;                                 \
        _Pragma("unroll")                                                     \
        for (int q = 0; q < 2; ++q) {                                         \
            int r = cr + q * 64;                                              \
            uint32_t d = db + r * 128 + ((cu ^ (r & 7)) << 4);                \
            size_t eA = (size_t)(row0 + r) * HH + k0e + cu * 8;               \
            size_t eB = (size_t)(col0 + r) * HH + k0e + cu * 8;               \
            CP16(d,                 (const char*)(Ahi + eA));                 \
            CP16(d + MAT_BYTES,     (const char*)(Alo + eA));                 \
            CP16(d + 2 * MAT_BYTES, (const char*)(Bhi + eB));                 \
        }                                                                     \
        CP_COMMIT();                                                          \
    } while (0)

    LOAD_CHUNK(0, 0);

    for (int i = 0; i < NCHUNK; ++i) {
        if (i < NCHUNK - 1) { LOAD_CHUNK((i + 1) & 1, i + 1); CP_WAIT(1); }
        else                { CP_WAIT(0); }
        __syncthreads();

        uint32_t base = sb + (i & 1) * STAGE_BYTES;
        #pragma unroll
        for (int kk = 0; kk < KCH; kk += 16) {
            uint32_t ah[2][4], al[2][4], bh[4][2];
            #pragma unroll
            for (int m = 0; m < 2; ++m) {
                int r = wr * 32 + m * 16 + a_row;
                int un = (kk >> 3) + a_un;
                uint32_t off = base + r * 128 + ((un ^ (r & 7)) << 4);
                LDM4(ah[m], off);
                LDM4(al[m], off + MAT_BYTES);
            }
            #pragma unroll
            for (int jp = 0; jp < 2; ++jp) {
                int r = wc * 32 + jp * 16 + b_row;
                int un = (kk >> 3) + b_un;
                uint32_t off = base + 2 * MAT_BYTES + r * 128 + ((un ^ (r & 7)) << 4);
                uint32_t t0[4];
                LDM4(t0, off);
                bh[2*jp][0] = t0[0]; bh[2*jp][1] = t0[1];
                bh[2*jp+1][0] = t0[2]; bh[2*jp+1][1] = t0[3];
            }
            #pragma unroll
            for (int m = 0; m < 2; ++m)
                #pragma unroll
                for (int j = 0; j < 4; ++j) {
                    MMAH(acc[m][j], ah[m], bh[j]);
                    MMAH(acc[m][j], al[m], bh[j]);
                }
        }
        __syncthreads();
    }

    // ---- epilogue: registers -> global (fused bias / relu / mix) ----
    int tr = lane >> 2;
    int tc = (lane & 3) * 2;
    #pragma unroll
    for (int m = 0; m < 2; ++m) {
        #pragma unroll
        for (int half = 0; half < 2; ++half) {
            int row = row0 + wr * 32 + m * 16 + half * 8 + tr;
            float msk = 0.f;
            if (MODE == 1) msk = (mixu[row] < P_MIX_C) ? 1.f : 0.f;
            #pragma unroll
            for (int j = 0; j < 4; ++j) {
                int col = col0 + wc * 32 + j * 8 + tc;
                float v0 = acc[m][j][half * 2 + 0] + bias[col];
                float v1 = acc[m][j][half * 2 + 1] + bias[col + 1];
                size_t idx = (size_t)row * HH + col;
                if (MODE == 0) {
                    v0 = fmaxf(v0, 0.f); v1 = fmaxf(v1, 0.f);
                    __half h0, l0, h1, l1;
                    split_f16(v0, h0, l0);
                    split_f16(v1, h1, l1);
                    *(uint32_t*)(yhi + idx) = pack2h(h0, h1);
                    *(uint32_t*)(ylo + idx) = pack2h(l0, l1);
                } else {
                    float2 fcv = make_float2(v0, v1);
                    *(float2*)(fcout + idx) = fcv;
                    float2 bm = fcv;
                    if (msk != 0.f) bm = *(const float2*)(bert + idx);
                    *(float2*)(outbm + idx) = bm;
                }
            }
        }
    }
}

// ---------------------------------------------------------------------------
extern "C" void kernel_launch(void* const* d_in, const int* in_sizes, int n_in,
                              void* d_out, int out_size) {
    const float* hs      = (const float*)d_in[0];
    const int*   lengths = (const int*)  d_in[1];
    const float* W1      = (const float*)d_in[2];
    const float* b1      = (const float*)d_in[3];
    const float* W2      = (const float*)d_in[4];
    const float* b2      = (const float*)d_in[5];
    const float* bert    = (const float*)d_in[6];
    const float* mixu    = (const float*)d_in[7];
    float* out = (float*)d_out;

    __half *sahi, *salo, *y1hi, *y1lo, *w1h, *w2h;
    cudaGetSymbolAddress((void**)&sahi, g_sa_hi);
    cudaGetSymbolAddress((void**)&salo, g_sa_lo);
    cudaGetSymbolAddress((void**)&y1hi, g_y1_hi);
    cudaGetSymbolAddress((void**)&y1lo, g_y1_lo);
    cudaGetSymbolAddress((void**)&w1h, g_w1t_hi);
    cudaGetSymbolAddress((void**)&w2h, g_w2t_hi);

    cudaFuncSetAttribute(gemm_hmma<0>, cudaFuncAttributeMaxDynamicSharedMemorySize, SMEM_SZ);
    cudaFuncSetAttribute(gemm_hmma<1>, cudaFuncAttributeMaxDynamicSharedMemorySize, SMEM_SZ);

    alpha_kernel<<<BB, 256>>>(hs, lengths);
    nhat_kernel<<<1, 32>>>(out + NHAT_OFF);
    wtrans_kernel<<<dim3(24, 24), dim3(32, 8)>>>(W1, w1h, HM1);
    wtrans_kernel<<<dim3(24, 24), dim3(32, 8)>>>(W2, w2h, HH);
    cif_scan_kernel<<<dim3(3, BB), 256>>>(hs);

    gemm_hmma<0><<<dim3(6, 100), 512, SMEM_SZ>>>(
        sahi, salo, w1h, b1, y1hi, y1lo,
        nullptr, nullptr, nullptr, nullptr);
    gemm_hmma<1><<<dim3(6, 100), 512, SMEM_SZ>>>(
        y1hi, y1lo, w2h, b2, nullptr, nullptr,
        out /*bert_mixing*/, out + FC_OFF /*fc*/, bert, mixu);
}

// round 8
// speedup vs baseline: 1.8119x; 1.3710x over previous
#include <cuda_runtime.h>
#include <cuda_fp16.h>
#include <math.h>
#include <stdint.h>

#define BB 32
#define TT 1500
#define HH 768
#define HM1 767
#define LQ 400
#define MM (BB*LQ)                 /* 12800 */
#define FC_OFF ((size_t)MM*HH)
#define NHAT_OFF ((size_t)2*MM*HH)
#define P_MIX_C 0.15f

// ---------------- scratch (__device__ globals, no allocs) ------------------
__device__ float g_scale[BB];
__device__ float g_nhat_part[BB];
__device__ __half g_sa[(size_t)MM * HH];
__device__ __half g_y1[(size_t)MM * HH];
__device__ __half g_w1t[(size_t)HH * HH];
__device__ __half g_w2t[(size_t)HH * HH];

// ---------------- helpers --------------------------------------------------
__device__ __forceinline__ uint32_t smem_u32(const void* p) {
    uint32_t a;
    asm("{ .reg .u64 t; cvta.to.shared.u64 t, %1; cvt.u32.u64 %0, t; }"
        : "=r"(a) : "l"(p));
    return a;
}
__device__ __forceinline__ uint32_t pack2h(__half a, __half b) {
    return (uint32_t)__half_as_ushort(a) |
           ((uint32_t)__half_as_ushort(b) << 16);
}

#define CP16(d, s) \
    asm volatile("cp.async.cg.shared.global [%0], [%1], 16;" :: "r"(d), "l"(s))
#define CP_COMMIT() asm volatile("cp.async.commit_group;" ::: "memory")
#define CP_WAIT(n)  asm volatile("cp.async.wait_group %0;" :: "n"(n) : "memory")

#define LDM4(r, addr) \
    asm volatile("ldmatrix.sync.aligned.m8n8.x4.shared.b16 {%0,%1,%2,%3},[%4];" \
        : "=r"((r)[0]), "=r"((r)[1]), "=r"((r)[2]), "=r"((r)[3]) : "r"(addr))

#define MMAH(d, a, b) \
    asm volatile("mma.sync.aligned.m16n8k16.row.col.f32.f16.f16.f32 " \
        "{%0,%1,%2,%3},{%4,%5,%6,%7},{%8,%9},{%0,%1,%2,%3};" \
        : "+f"((d)[0]), "+f"((d)[1]), "+f"((d)[2]), "+f"((d)[3]) \
        : "r"((a)[0]), "r"((a)[1]), "r"((a)[2]), "r"((a)[3]), \
          "r"((b)[0]), "r"((b)[1]))

// ---------------------------------------------------------------------------
// Kernel 1: per-batch alpha sum, scale, n_hat partial
// ---------------------------------------------------------------------------
__global__ void alpha_kernel(const float* __restrict__ hs,
                             const int* __restrict__ lengths) {
    int b = blockIdx.x;
    const float* base = hs + (size_t)b * TT * HH + (HH - 1);
    float s = 0.f;
    for (int t = threadIdx.x; t < TT; t += blockDim.x)
        s += 1.f / (1.f + expf(-base[(size_t)t * HH]));
    __shared__ float red[256];
    red[threadIdx.x] = s;
    __syncthreads();
    for (int o = 128; o > 0; o >>= 1) {
        if (threadIdx.x < o) red[threadIdx.x] += red[threadIdx.x + o];
        __syncthreads();
    }
    if (threadIdx.x == 0) {
        float sum = red[0];
        int li = lengths[b];
        float tll = (float)(li < LQ ? li : LQ);
        g_scale[b] = tll / sum;
        float d = tll - sum;
        g_nhat_part[b] = d * d;
    }
}
__global__ void nhat_kernel(float* __restrict__ out) {
    float v = g_nhat_part[threadIdx.x];
    #pragma unroll
    for (int o = 16; o > 0; o >>= 1) v += __shfl_down_sync(0xffffffffu, v, o);
    if (threadIdx.x == 0) out[0] = v;
}

// ---------------------------------------------------------------------------
// Kernel 2: CIF scan -> fp16 plane. Pad lane 767 -> zeros.
// ---------------------------------------------------------------------------
__global__ void cif_scan_kernel(const float* __restrict__ hs) {
    int b = blockIdx.y;
    int f = blockIdx.x * blockDim.x + threadIdx.x;
    __shared__ float s_alpha[LQ];
    float scale = g_scale[b];
    const float* hb = hs + (size_t)b * TT * HH;
    for (int t = threadIdx.x; t < LQ; t += blockDim.x)
        s_alpha[t] = scale / (1.f + expf(-hb[(size_t)t * HH + (HH - 1)]));
    __syncthreads();

    bool valid = (f < HM1);
    const float* hcol = hb + f;
    size_t obase = (size_t)b * LQ * HH + f;

    float a_r = 0.f, s_r = 0.f;
    float h = valid ? hcol[0] : 0.f;
    for (int t = 0; t < LQ; ++t) {
        float hn = valid ? hcol[(size_t)(t + 1) * HH] : 0.f;
        float a = s_alpha[t];
        float a_a = a + a_r;
        float rem = 1.0f - a_r;
        float s_a_nf = s_r + a * h;
        float s_a;
        if (a_a >= 1.0f) {
            float a_r_f = a - rem;
            s_a = s_r + rem * h;
            a_r = a_r_f;
            s_r = a_r_f * h;
        } else {
            a_r = a_a; s_a = s_a_nf; s_r = s_a_nf;
        }
        g_sa[obase + (size_t)t * HH] = __float2half_rn(s_a);
        h = hn;
    }
}

// ---------------------------------------------------------------------------
// Kernel 3: W transpose: Wt[n][k] = fp16(W[k][n]), k>=Kvalid -> 0
// ---------------------------------------------------------------------------
__global__ void wtrans_kernel(const float* __restrict__ W,
                              __half* __restrict__ Wt, int Kvalid) {
    __shared__ float t[32][33];
    int n = blockIdx.x * 32 + threadIdx.x;
    #pragma unroll
    for (int j = 0; j < 32; j += 8) {
        int k = blockIdx.y * 32 + threadIdx.y + j;
        t[threadIdx.y + j][threadIdx.x] = (k < Kvalid) ? W[(size_t)k * HH + n] : 0.f;
    }
    __syncthreads();
    #pragma unroll
    for (int j = 0; j < 32; j += 8) {
        int nn = blockIdx.x * 32 + threadIdx.y + j;
        int kk = blockIdx.y * 32 + threadIdx.x;
        Wt[(size_t)nn * HH + kk] = __float2half_rn(t[threadIdx.x][threadIdx.y + j]);
    }
}

// ---------------------------------------------------------------------------
// Kernel 4: single-term fp16 HMMA GEMM (C = Ah*Bh). CTA tile 128x128, 512
// threads / 16 warps (4x4, warp tile 32x32). K chunks of 64, 2-stage
// cp.async pipeline, XOR-swizzled SMEM.
// MODE 0: y1 = relu(A@B^T+b) -> fp16. MODE 1: fc + bert_mixing.
// ---------------------------------------------------------------------------
#define KCH 64
#define NCHUNK (HH / KCH)            /* 12 */
#define MAT_BYTES 16384              /* 128 rows x 128B */
#define STAGE_BYTES (2 * MAT_BYTES)  /* 32768: A, B */
#define SMEM_SZ (2 * STAGE_BYTES)    /* 65536 */

template <int MODE>
__global__ void __launch_bounds__(512, 1)
gemm_hmma(const __half* __restrict__ Ah, const __half* __restrict__ Bh,
          const float* __restrict__ bias,
          __half* __restrict__ yout,
          float* __restrict__ outbm, float* __restrict__ fcout,
          const float* __restrict__ bert, const float* __restrict__ mixu) {
    extern __shared__ char smem[];
    uint32_t sb = smem_u32(smem);
    int tid = threadIdx.x, lane = tid & 31, wid = tid >> 5;
    int row0 = blockIdx.y * 128, col0 = blockIdx.x * 128;
    int wr = wid >> 2, wc = wid & 3;     // warp tile: rows wr*32, cols wc*32

    float acc[2][4][4];
    #pragma unroll
    for (int i = 0; i < 2; ++i)
        #pragma unroll
        for (int j = 0; j < 4; ++j)
            #pragma unroll
            for (int d = 0; d < 4; ++d) acc[i][j][d] = 0.f;

    int cr = tid >> 3, cu = tid & 7;

    int a_row = lane & 15;
    int a_un  = lane >> 4;
    int b_row = (lane & 7) + ((lane & 16) >> 1);
    int b_un  = (lane & 8) >> 3;

    #define LOAD_CHUNK(s, ci) do {                                            \
        int k0e = (ci) * KCH;                                                 \
        uint32_t db = sb + (s) * STAGE_BYTES;                                 \
        _Pragma("unroll")                                                     \
        for (int q = 0; q < 2; ++q) {                                         \
            int r = cr + q * 64;                                              \
            uint32_t d = db + r * 128 + ((cu ^ (r & 7)) << 4);                \
            size_t eA = (size_t)(row0 + r) * HH + k0e + cu * 8;               \
            size_t eB = (size_t)(col0 + r) * HH + k0e + cu * 8;               \
            CP16(d,             (const char*)(Ah + eA));                      \
            CP16(d + MAT_BYTES, (const char*)(Bh + eB));                      \
        }                                                                     \
        CP_COMMIT();                                                          \
    } while (0)

    LOAD_CHUNK(0, 0);

    for (int i = 0; i < NCHUNK; ++i) {
        if (i < NCHUNK - 1) { LOAD_CHUNK((i + 1) & 1, i + 1); CP_WAIT(1); }
        else                { CP_WAIT(0); }
        __syncthreads();

        uint32_t base = sb + (i & 1) * STAGE_BYTES;
        #pragma unroll
        for (int kk = 0; kk < KCH; kk += 16) {
            uint32_t ah[2][4], bh[4][2];
            #pragma unroll
            for (int m = 0; m < 2; ++m) {
                int r = wr * 32 + m * 16 + a_row;
                int un = (kk >> 3) + a_un;
                uint32_t off = base + r * 128 + ((un ^ (r & 7)) << 4);
                LDM4(ah[m], off);
            }
            #pragma unroll
            for (int jp = 0; jp < 2; ++jp) {
                int r = wc * 32 + jp * 16 + b_row;
                int un = (kk >> 3) + b_un;
                uint32_t off = base + MAT_BYTES + r * 128 + ((un ^ (r & 7)) << 4);
                uint32_t t0[4];
                LDM4(t0, off);
                bh[2*jp][0] = t0[0]; bh[2*jp][1] = t0[1];
                bh[2*jp+1][0] = t0[2]; bh[2*jp+1][1] = t0[3];
            }
            #pragma unroll
            for (int m = 0; m < 2; ++m)
                #pragma unroll
                for (int j = 0; j < 4; ++j)
                    MMAH(acc[m][j], ah[m], bh[j]);
        }
        __syncthreads();
    }

    // ---- epilogue: registers -> global (fused bias / relu / mix) ----
    int tr = lane >> 2;
    int tc = (lane & 3) * 2;
    #pragma unroll
    for (int m = 0; m < 2; ++m) {
        #pragma unroll
        for (int half = 0; half < 2; ++half) {
            int row = row0 + wr * 32 + m * 16 + half * 8 + tr;
            float msk = 0.f;
            if (MODE == 1) msk = (mixu[row] < P_MIX_C) ? 1.f : 0.f;
            #pragma unroll
            for (int j = 0; j < 4; ++j) {
                int col = col0 + wc * 32 + j * 8 + tc;
                float v0 = acc[m][j][half * 2 + 0] + bias[col];
                float v1 = acc[m][j][half * 2 + 1] + bias[col + 1];
                size_t idx = (size_t)row * HH + col;
                if (MODE == 0) {
                    v0 = fmaxf(v0, 0.f); v1 = fmaxf(v1, 0.f);
                    *(uint32_t*)(yout + idx) =
                        pack2h(__float2half_rn(v0), __float2half_rn(v1));
                } else {
                    float2 fcv = make_float2(v0, v1);
                    *(float2*)(fcout + idx) = fcv;
                    float2 bm = fcv;
                    if (msk != 0.f) bm = *(const float2*)(bert + idx);
                    *(float2*)(outbm + idx) = bm;
                }
            }
        }
    }
}

// ---------------------------------------------------------------------------
extern "C" void kernel_launch(void* const* d_in, const int* in_sizes, int n_in,
                              void* d_out, int out_size) {
    const float* hs      = (const float*)d_in[0];
    const int*   lengths = (const int*)  d_in[1];
    const float* W1      = (const float*)d_in[2];
    const float* b1      = (const float*)d_in[3];
    const float* W2      = (const float*)d_in[4];
    const float* b2      = (const float*)d_in[5];
    const float* bert    = (const float*)d_in[6];
    const float* mixu    = (const float*)d_in[7];
    float* out = (float*)d_out;

    __half *sa, *y1, *w1t, *w2t;
    cudaGetSymbolAddress((void**)&sa, g_sa);
    cudaGetSymbolAddress((void**)&y1, g_y1);
    cudaGetSymbolAddress((void**)&w1t, g_w1t);
    cudaGetSymbolAddress((void**)&w2t, g_w2t);

    cudaFuncSetAttribute(gemm_hmma<0>, cudaFuncAttributeMaxDynamicSharedMemorySize, SMEM_SZ);
    cudaFuncSetAttribute(gemm_hmma<1>, cudaFuncAttributeMaxDynamicSharedMemorySize, SMEM_SZ);

    alpha_kernel<<<BB, 256>>>(hs, lengths);
    nhat_kernel<<<1, 32>>>(out + NHAT_OFF);
    wtrans_kernel<<<dim3(24, 24), dim3(32, 8)>>>(W1, w1t, HM1);
    wtrans_kernel<<<dim3(24, 24), dim3(32, 8)>>>(W2, w2t, HH);
    cif_scan_kernel<<<dim3(3, BB), 256>>>(hs);

    gemm_hmma<0><<<dim3(6, 100), 512, SMEM_SZ>>>(
        sa, w1t, b1, y1, nullptr, nullptr, nullptr, nullptr);
    gemm_hmma<1><<<dim3(6, 100), 512, SMEM_SZ>>>(
        y1, w2t, b2, nullptr,
        out /*bert_mixing*/, out + FC_OFF /*fc*/, bert, mixu);
}